// round 1
// baseline (speedup 1.0000x reference)
#include <cuda_runtime.h>
#include <cuda_bf16.h>

// Problem constants (fixed by the reference)
#define NVSEG 29000
#define HWSZ  (1024 * 1024)
#define BATCH 16
#define BHW   (BATCH * HWSZ)

// Scratch (allocation-free rule: __device__ globals)
// g_acc[v] = {sum_c0, sum_c1, sum_c2, count}
__device__ float4 g_acc[NVSEG];
// g_rep[v] = {fV0 - mean0, fV1 - mean1, fV2 - mean2, unused}
__device__ float4 g_rep[NVSEG];

__global__ __launch_bounds__(256) void zero_acc_kernel() {
    int i = blockIdx.x * blockDim.x + threadIdx.x;
    if (i < NVSEG) g_acc[i] = make_float4(0.f, 0.f, 0.f, 0.f);
}

// Pass 1: segment sums + counts. 4 pixels per thread, one float4 RED per pixel.
__global__ __launch_bounds__(256) void accumulate_kernel(
    const float* __restrict__ img, const int* __restrict__ seg)
{
    const long t = (long)blockIdx.x * blockDim.x + threadIdx.x;  // 0 .. BHW/4
    const long p = t << 2;                 // first pixel index
    const int  b = (int)(t >> 18);         // p >> 20 (HW = 2^20)
    const long rem = p & (HWSZ - 1);       // spatial offset within image
    const float* base = img + (long)b * 3 * HWSZ + rem;

    const float4 c0 = *(const float4*)(base + 0 * HWSZ);
    const float4 c1 = *(const float4*)(base + 1 * HWSZ);
    const float4 c2 = *(const float4*)(base + 2 * HWSZ);
    const int4   s  = *(const int4*)(seg + p);

#if __CUDA_ARCH__ >= 900
    atomicAdd(&g_acc[s.x], make_float4(c0.x, c1.x, c2.x, 1.0f));
    atomicAdd(&g_acc[s.y], make_float4(c0.y, c1.y, c2.y, 1.0f));
    atomicAdd(&g_acc[s.z], make_float4(c0.z, c1.z, c2.z, 1.0f));
    atomicAdd(&g_acc[s.w], make_float4(c0.w, c1.w, c2.w, 1.0f));
#else
    float* a;
    a = (float*)&g_acc[s.x];
    atomicAdd(a + 0, c0.x); atomicAdd(a + 1, c1.x); atomicAdd(a + 2, c2.x); atomicAdd(a + 3, 1.0f);
    a = (float*)&g_acc[s.y];
    atomicAdd(a + 0, c0.y); atomicAdd(a + 1, c1.y); atomicAdd(a + 2, c2.y); atomicAdd(a + 3, 1.0f);
    a = (float*)&g_acc[s.z];
    atomicAdd(a + 0, c0.z); atomicAdd(a + 1, c1.z); atomicAdd(a + 2, c2.z); atomicAdd(a + 3, 1.0f);
    a = (float*)&g_acc[s.w];
    atomicAdd(a + 0, c0.w); atomicAdd(a + 1, c1.w); atomicAdd(a + 2, c2.w); atomicAdd(a + 3, 1.0f);
#endif
}

// Pass 2: replaced_mean[v] = fV[v] - sums[v] / max(count, 1)
__global__ __launch_bounds__(256) void replaced_kernel(const float* __restrict__ fV) {
    int v = blockIdx.x * blockDim.x + threadIdx.x;
    if (v >= NVSEG) return;
    float4 a = g_acc[v];
    float inv = 1.0f / fmaxf(a.w, 1.0f);
    float4 r;
    r.x = fV[3 * v + 0] - a.x * inv;
    r.y = fV[3 * v + 1] - a.y * inv;
    r.z = fV[3 * v + 2] - a.z * inv;
    r.w = 0.f;
    g_rep[v] = r;
}

// Pass 3: out[p, c] = pixels[p, c] + replaced[seg[p], c]
// 4 pixels / thread -> 12 output floats = 3 aligned float4 stores.
__global__ __launch_bounds__(256) void output_kernel(
    const float* __restrict__ img, const int* __restrict__ seg,
    float* __restrict__ out)
{
    const long t = (long)blockIdx.x * blockDim.x + threadIdx.x;
    const long p = t << 2;
    const int  b = (int)(t >> 18);
    const long rem = p & (HWSZ - 1);
    const float* base = img + (long)b * 3 * HWSZ + rem;

    const float4 c0 = *(const float4*)(base + 0 * HWSZ);
    const float4 c1 = *(const float4*)(base + 1 * HWSZ);
    const float4 c2 = *(const float4*)(base + 2 * HWSZ);
    const int4   s  = *(const int4*)(seg + p);

    const float4 r0 = g_rep[s.x];
    const float4 r1 = g_rep[s.y];
    const float4 r2 = g_rep[s.z];
    const float4 r3 = g_rep[s.w];

    // Interleave to [pixel, channel] row-major
    float4 o0, o1, o2;
    o0.x = c0.x + r0.x;  o0.y = c1.x + r0.y;  o0.z = c2.x + r0.z;  o0.w = c0.y + r1.x;
    o1.x = c1.y + r1.y;  o1.y = c2.y + r1.z;  o1.z = c0.z + r2.x;  o1.w = c1.z + r2.y;
    o2.x = c2.z + r2.z;  o2.y = c0.w + r3.x;  o2.z = c1.w + r3.y;  o2.w = c2.w + r3.z;

    float4* dst = (float4*)(out + p * 3);   // 12t floats -> 16B aligned
    dst[0] = o0;
    dst[1] = o1;
    dst[2] = o2;
}

extern "C" void kernel_launch(void* const* d_in, const int* in_sizes, int n_in,
                              void* d_out, int out_size)
{
    const float* img = (const float*)d_in[0];
    const int*   seg = (const int*)d_in[1];
    const float* fV  = (const float*)d_in[2];
    float* out = (float*)d_out;

    const int threads = 256;
    const int nvBlocks = (NVSEG + threads - 1) / threads;
    const int pixBlocks = (BHW / 4) / threads;   // 16384

    zero_acc_kernel<<<nvBlocks, threads>>>();
    accumulate_kernel<<<pixBlocks, threads>>>(img, seg);
    replaced_kernel<<<nvBlocks, threads>>>(fV);
    output_kernel<<<pixBlocks, threads>>>(img, seg, out);
}